// round 4
// baseline (speedup 1.0000x reference)
#include <cuda_runtime.h>
#include <cstdint>

// ---------------- problem constants ----------------
#define NN     50000
#define FDIM   128
#define EMAX   600000

// ---------------- device scratch ----------------
__device__ float    g_t[(size_t)NN * FDIM];   // GEMM output (pre-aggregation)
__device__ float    g_h[(size_t)NN * FDIM];   // layer activations
__device__ uint32_t g_Bp[3][16384];           // pre-permuted tf32 W fragments
__device__ int      g_cnt[NN];
__device__ int      g_cnt2[NN];
__device__ int      g_rowptr[NN + 1];
__device__ float    g_dinv[NN];
__device__ int      g_esrc[EMAX];
__device__ float    g_enorm[EMAX];

__device__ __forceinline__ uint32_t cvt_tf32(float f) {
    uint32_t r; asm("cvt.rna.tf32.f32 %0, %1;" : "=r"(r) : "f"(f)); return r;
}

// ---------------- setup kernels ----------------
__global__ void k_zero_counts(int n) {
    int i = blockIdx.x * blockDim.x + threadIdx.x;
    if (i < n) { g_cnt[i] = 0; g_cnt2[i] = 0; }
}

__global__ void k_count(const int* __restrict__ ei, int E) {
    int e = blockIdx.x * blockDim.x + threadIdx.x;
    if (e < E) atomicAdd(&g_cnt[ei[E + e]], 1);   // dst = row 1
}

// single-block fused scan: rowptr (exclusive) + dinv
__global__ __launch_bounds__(1024) void k_scanfused(int n, int E) {
    __shared__ int s[1024];
    const int tid = threadIdx.x;
    const int PER = (n + 1023) >> 10;
    int start = tid * PER;
    int end = start + PER; if (end > n) end = n;

    int sum = 0;
    for (int i = start; i < end; i++) sum += g_cnt[i];
    s[tid] = sum;
    __syncthreads();
    for (int off = 1; off < 1024; off <<= 1) {
        int t = (tid >= off) ? s[tid - off] : 0;
        __syncthreads();
        s[tid] += t;
        __syncthreads();
    }
    int run = s[tid] - sum;   // exclusive base for this thread's chunk
    for (int i = start; i < end; i++) {
        int v = g_cnt[i];
        g_rowptr[i] = run;
        g_dinv[i] = rsqrtf((float)(v + 1));   // +1 self loop
        run += v;
    }
    if (tid == 0) g_rowptr[n] = E;
}

__global__ void k_scatter(const int* __restrict__ ei, int E) {
    int e = blockIdx.x * blockDim.x + threadIdx.x;
    if (e >= E) return;
    int s = ei[e];
    int d = ei[E + e];
    int pos = g_rowptr[d] + atomicAdd(&g_cnt2[d], 1);
    g_esrc[pos]  = s;
    g_enorm[pos] = g_dinv[s] * g_dinv[d];
}

// pre-permute all 3 weight matrices into lane-packed tf32 fragment layout:
// slot=(nt*16+kt)*32+lane; b0=W[kt*8+tg][nt*8+g], b1=W[kt*8+tg+4][nt*8+g]
__global__ __launch_bounds__(256) void k_bperm3(const float* __restrict__ W1,
                                                const float* __restrict__ W2,
                                                const float* __restrict__ W3) {
    int l = blockIdx.x >> 5;
    const float* W = (l == 0) ? W1 : (l == 1) ? W2 : W3;
    uint32_t* Bp = g_Bp[l];
    int slot = (blockIdx.x & 31) * 256 + threadIdx.x;   // 8192 slots/layer
    int lane = slot & 31;
    int group = slot >> 5;
    int nt = group >> 4, kt = group & 15;
    int g = lane >> 2, tg = lane & 3;
    Bp[slot * 2]     = cvt_tf32(W[(kt * 8 + tg) * 128 + nt * 8 + g]);
    Bp[slot * 2 + 1] = cvt_tf32(W[(kt * 8 + tg + 4) * 128 + nt * 8 + g]);
}

// ---------------- tf32 mma.sync GEMM ----------------
// C[row0:+128, 0:128] = A[rows,128] @ W; 8 warps, each 32x64; m16n8k8.
// A in smem (pitch 132, conflict-free fragment gather); B fragments from gmem (L2).

#define APITCH 132
#define SMEM_GEMM (128 * APITCH * 4)

__device__ __forceinline__ void mma_tf32(float* c, const uint32_t* a, const uint32_t* b) {
    asm volatile(
        "mma.sync.aligned.m16n8k8.row.col.f32.tf32.tf32.f32 "
        "{%0,%1,%2,%3}, {%4,%5,%6,%7}, {%8,%9}, {%0,%1,%2,%3};"
        : "+f"(c[0]), "+f"(c[1]), "+f"(c[2]), "+f"(c[3])
        : "r"(a[0]), "r"(a[1]), "r"(a[2]), "r"(a[3]), "r"(b[0]), "r"(b[1]));
}

__global__ __launch_bounds__(256) void k_gemm_mma(const float* __restrict__ A,
                                                  const uint32_t* __restrict__ Bp,
                                                  float* __restrict__ C, int nrows) {
    extern __shared__ float sm[];
    uint32_t* Apu = (uint32_t*)sm;         // [128][132] tf32 bits

    const int tid  = threadIdx.x;
    const int lane = tid & 31;
    const int wid  = tid >> 5;
    const int row0 = blockIdx.x * 128;

    // ---- stage A tile (tf32-rounded), coalesced + guarded
#pragma unroll
    for (int i = 0; i < 16; i++) {
        int idx = i * 256 + tid;
        int r  = idx >> 5;
        int k4 = idx & 31;
        float4 v = make_float4(0.f, 0.f, 0.f, 0.f);
        if (row0 + r < nrows)
            v = ((const float4*)(A + (size_t)(row0 + r) * 128))[k4];
        uint32_t* p = Apu + r * APITCH + k4 * 4;
        p[0] = cvt_tf32(v.x); p[1] = cvt_tf32(v.y);
        p[2] = cvt_tf32(v.z); p[3] = cvt_tf32(v.w);
    }
    __syncthreads();

    const int wrow = wid >> 1;
    const int wcol = wid & 1;
    const int g = lane >> 2, tg = lane & 3;

    float acc[2][8][4];
#pragma unroll
    for (int i = 0; i < 2; i++)
#pragma unroll
        for (int j = 0; j < 8; j++)
#pragma unroll
            for (int q = 0; q < 4; q++) acc[i][j][q] = 0.f;

    // B fragment base for this warp's column band
    const uint32_t* BpBase = Bp + ((size_t)(wcol * 8) * 16) * 64 + lane * 2;

#pragma unroll 4
    for (int kt = 0; kt < 16; kt++) {
        uint32_t bf[8][2];
#pragma unroll
        for (int j = 0; j < 8; j++) {
            uint2 bv = *(const uint2*)(BpBase + (size_t)(j * 16 + kt) * 64);
            bf[j][0] = bv.x; bf[j][1] = bv.y;
        }
        uint32_t af[2][4];
#pragma unroll
        for (int i = 0; i < 2; i++) {
            int r = wrow * 32 + i * 16 + g;
            int c = kt * 8 + tg;
            af[i][0] = Apu[r * APITCH + c];
            af[i][1] = Apu[(r + 8) * APITCH + c];
            af[i][2] = Apu[r * APITCH + c + 4];
            af[i][3] = Apu[(r + 8) * APITCH + c + 4];
        }
#pragma unroll
        for (int i = 0; i < 2; i++)
#pragma unroll
            for (int j = 0; j < 8; j++)
                mma_tf32(acc[i][j], af[i], bf[j]);
    }

    // ---- epilogue: direct v2 stores
#pragma unroll
    for (int i = 0; i < 2; i++) {
        int r = row0 + wrow * 32 + i * 16 + g;
#pragma unroll
        for (int j = 0; j < 8; j++) {
            int col = wcol * 64 + j * 8 + tg * 2;
            if (r < nrows)
                *(float2*)(C + (size_t)r * 128 + col) =
                    make_float2(acc[i][j][0], acc[i][j][1]);
            if (r + 8 < nrows)
                *(float2*)(C + (size_t)(r + 8) * 128 + col) =
                    make_float2(acc[i][j][2], acc[i][j][3]);
        }
    }
}

// ---------------- aggregation ----------------
__global__ __launch_bounds__(128) void k_aggregate(const float* __restrict__ H,
                                                   const float* __restrict__ bias,
                                                   float* __restrict__ out,
                                                   float* __restrict__ out2,
                                                   int n, int relu) {
    int warp = threadIdx.x >> 5;
    int lane = threadIdx.x & 31;
    int node = blockIdx.x * 4 + warp;
    if (node >= n) return;

    float di = g_dinv[node];
    float di2 = di * di;
    float4 self = *(const float4*)(H + (size_t)node * 128 + lane * 4);
    float4 a0 = make_float4(self.x * di2, self.y * di2, self.z * di2, self.w * di2);
    float4 a1 = make_float4(0.f, 0.f, 0.f, 0.f);

    int e0 = g_rowptr[node], e1 = g_rowptr[node + 1];
    int e = e0;
    for (; e + 1 < e1; e += 2) {
        int   s0 = g_esrc[e],  s1 = g_esrc[e + 1];
        float m0 = g_enorm[e], m1 = g_enorm[e + 1];
        float4 h0 = *(const float4*)(H + (size_t)s0 * 128 + lane * 4);
        float4 h1 = *(const float4*)(H + (size_t)s1 * 128 + lane * 4);
        a0.x = fmaf(h0.x, m0, a0.x); a0.y = fmaf(h0.y, m0, a0.y);
        a0.z = fmaf(h0.z, m0, a0.z); a0.w = fmaf(h0.w, m0, a0.w);
        a1.x = fmaf(h1.x, m1, a1.x); a1.y = fmaf(h1.y, m1, a1.y);
        a1.z = fmaf(h1.z, m1, a1.z); a1.w = fmaf(h1.w, m1, a1.w);
    }
    if (e < e1) {
        int   s0 = g_esrc[e];
        float m0 = g_enorm[e];
        float4 h0 = *(const float4*)(H + (size_t)s0 * 128 + lane * 4);
        a0.x = fmaf(h0.x, m0, a0.x); a0.y = fmaf(h0.y, m0, a0.y);
        a0.z = fmaf(h0.z, m0, a0.z); a0.w = fmaf(h0.w, m0, a0.w);
    }

    float4 b = *(const float4*)(bias + lane * 4);
    float4 o = make_float4(a0.x + a1.x + b.x, a0.y + a1.y + b.y,
                           a0.z + a1.z + b.z, a0.w + a1.w + b.w);
    if (relu) {
        o.x = fmaxf(o.x, 0.f); o.y = fmaxf(o.y, 0.f);
        o.z = fmaxf(o.z, 0.f); o.w = fmaxf(o.w, 0.f);
    }
    size_t off = (size_t)node * 128 + lane * 4;
    *(float4*)(out + off) = o;
    if (out2) *(float4*)(out2 + off) = o;
}

// ---------------- launch ----------------
extern "C" void kernel_launch(void* const* d_in, const int* in_sizes, int n_in,
                              void* d_out, int out_size) {
    const float* x  = (const float*)d_in[0];
    const int*   ei = (const int*)d_in[1];
    const float* W1 = (const float*)d_in[2];
    const float* b1 = (const float*)d_in[3];
    const float* W2 = (const float*)d_in[4];
    const float* b2 = (const float*)d_in[5];
    const float* W3 = (const float*)d_in[6];
    const float* b3 = (const float*)d_in[7];

    int N = in_sizes[0] / FDIM;
    if (N > NN) N = NN;
    int E = in_sizes[1] / 2;
    if (E > EMAX) E = EMAX;

    static float* t = nullptr;
    static float* h = nullptr;
    static uint32_t* bp = nullptr;
    static bool inited = false;
    if (!inited) {
        cudaGetSymbolAddress((void**)&t, g_t);
        cudaGetSymbolAddress((void**)&h, g_h);
        cudaGetSymbolAddress((void**)&bp, g_Bp);
        cudaFuncSetAttribute(k_gemm_mma, cudaFuncAttributeMaxDynamicSharedMemorySize,
                             SMEM_GEMM);
        inited = true;
    }
    uint32_t* Bp1 = bp;
    uint32_t* Bp2 = bp + 16384;
    uint32_t* Bp3 = bp + 2 * 16384;

    // weight fragment pre-permute + CSR build
    k_bperm3<<<96, 256>>>(W1, W2, W3);
    k_zero_counts<<<(N + 255) / 256, 256>>>(N);
    k_count<<<(E + 255) / 256, 256>>>(ei, E);
    k_scanfused<<<1, 1024>>>(N, E);
    k_scatter<<<(E + 255) / 256, 256>>>(ei, E);

    const int gGemm = (N + 127) / 128;
    const int gAgg  = (N + 3) / 4;
    float* out = (float*)d_out;
    int half = N * FDIM;
    float* out2 = (out_size >= 2 * half) ? out + half : nullptr;

    k_gemm_mma<<<gGemm, 256, SMEM_GEMM>>>(x, Bp1, t, N);
    k_aggregate<<<gAgg, 128>>>(t, b1, h, nullptr, N, 1);
    k_gemm_mma<<<gGemm, 256, SMEM_GEMM>>>(h, Bp2, t, N);
    k_aggregate<<<gAgg, 128>>>(t, b2, h, nullptr, N, 1);
    k_gemm_mma<<<gGemm, 256, SMEM_GEMM>>>(h, Bp3, t, N);
    k_aggregate<<<gAgg, 128>>>(t, b3, out, out2, N, 0);
}

// round 5
// speedup vs baseline: 1.5380x; 1.5380x over previous
#include <cuda_runtime.h>
#include <cuda_fp16.h>
#include <cstdint>

// ---------------- problem constants ----------------
#define NN     50000
#define FDIM   128
#define EMAX   600000

// ---------------- device scratch ----------------
__device__ float    g_t[(size_t)NN * FDIM];   // reused as __half store (GEMM out)
__device__ float    g_h[(size_t)NN * FDIM];   // layer activations (fp32)
__device__ uint32_t g_Bp[3][16384];           // pre-permuted tf32 W fragments
__device__ int      g_cnt[NN];
__device__ int      g_cnt2[NN];
__device__ int      g_rowptr[NN + 1];
__device__ int      g_bsums[64];
__device__ float    g_dinv[NN];
__device__ int      g_esrc[EMAX];
__device__ float    g_enorm[EMAX];

__device__ __forceinline__ uint32_t cvt_tf32(float f) {
    uint32_t r; asm("cvt.rna.tf32.f32 %0, %1;" : "=r"(r) : "f"(f)); return r;
}

// ---------------- setup kernels ----------------
__global__ void k_count(const int* __restrict__ ei, int E) {
    int e = blockIdx.x * blockDim.x + threadIdx.x;
    if (e < E) atomicAdd(&g_cnt[ei[E + e]], 1);   // dst = row 1
}

// coalesced block-level exclusive scan + fused dinv
__global__ __launch_bounds__(1024) void k_scan1(int n) {
    __shared__ int s[1024];
    int i = blockIdx.x * 1024 + threadIdx.x;
    int v = (i < n) ? g_cnt[i] : 0;
    if (i < n) g_dinv[i] = rsqrtf((float)(v + 1));   // +1 self loop
    s[threadIdx.x] = v;
    __syncthreads();
    for (int off = 1; off < 1024; off <<= 1) {
        int t = (threadIdx.x >= off) ? s[threadIdx.x - off] : 0;
        __syncthreads();
        s[threadIdx.x] += t;
        __syncthreads();
    }
    if (i < n) g_rowptr[i] = s[threadIdx.x] - v;
    if (threadIdx.x == 1023) g_bsums[blockIdx.x] = s[1023];
}

// per-block prefix of bsums computed with a 64-lane parallel reduce (nb <= 49)
__global__ __launch_bounds__(1024) void k_scan3b(int n, int E) {
    __shared__ int red[64];
    const int bid = blockIdx.x;
    const int tid = threadIdx.x;
    if (tid < 64) red[tid] = (tid < bid) ? g_bsums[tid] : 0;
    __syncthreads();
    if (tid < 32) {
        int v = red[tid] + red[tid + 32];
#pragma unroll
        for (int o = 16; o; o >>= 1) v += __shfl_down_sync(0xffffffffu, v, o);
        if (tid == 0) red[0] = v;
    }
    __syncthreads();
    int pre = red[0];
    int i = bid * 1024 + tid;
    if (i < n) g_rowptr[i] += pre;
    if (i == 0) g_rowptr[n] = E;
}

__global__ void k_scatter(const int* __restrict__ ei, int E) {
    int e = blockIdx.x * blockDim.x + threadIdx.x;
    if (e >= E) return;
    int s = ei[e];
    int d = ei[E + e];
    int pos = g_rowptr[d] + atomicAdd(&g_cnt2[d], 1);
    g_esrc[pos]  = s;
    g_enorm[pos] = g_dinv[s] * g_dinv[d];
}

// pre-permute all 3 weight matrices into lane-packed tf32 fragment layout
__global__ __launch_bounds__(256) void k_bperm3(const float* __restrict__ W1,
                                                const float* __restrict__ W2,
                                                const float* __restrict__ W3) {
    int l = blockIdx.x >> 5;
    const float* W = (l == 0) ? W1 : (l == 1) ? W2 : W3;
    uint32_t* Bp = g_Bp[l];
    int slot = (blockIdx.x & 31) * 256 + threadIdx.x;   // 8192 slots/layer
    int lane = slot & 31;
    int group = slot >> 5;
    int nt = group >> 4, kt = group & 15;
    int g = lane >> 2, tg = lane & 3;
    Bp[slot * 2]     = cvt_tf32(W[(kt * 8 + tg) * 128 + nt * 8 + g]);
    Bp[slot * 2 + 1] = cvt_tf32(W[(kt * 8 + tg + 4) * 128 + nt * 8 + g]);
}

// ---------------- tf32 mma.sync GEMM (fp16 output) ----------------
#define APITCH 132
#define SMEM_GEMM (128 * APITCH * 4)

__device__ __forceinline__ void mma_tf32(float* c, const uint32_t* a, const uint32_t* b) {
    asm volatile(
        "mma.sync.aligned.m16n8k8.row.col.f32.tf32.tf32.f32 "
        "{%0,%1,%2,%3}, {%4,%5,%6,%7}, {%8,%9}, {%0,%1,%2,%3};"
        : "+f"(c[0]), "+f"(c[1]), "+f"(c[2]), "+f"(c[3])
        : "r"(a[0]), "r"(a[1]), "r"(a[2]), "r"(a[3]), "r"(b[0]), "r"(b[1]));
}

__global__ __launch_bounds__(256) void k_gemm_mma(const float* __restrict__ A,
                                                  const uint32_t* __restrict__ Bp,
                                                  __half* __restrict__ C, int nrows) {
    extern __shared__ float sm[];
    uint32_t* Apu = (uint32_t*)sm;         // [128][132] tf32 bits

    const int tid  = threadIdx.x;
    const int lane = tid & 31;
    const int wid  = tid >> 5;
    const int row0 = blockIdx.x * 128;

    // stage A tile (tf32-rounded), coalesced + guarded
#pragma unroll
    for (int i = 0; i < 16; i++) {
        int idx = i * 256 + tid;
        int r  = idx >> 5;
        int k4 = idx & 31;
        float4 v = make_float4(0.f, 0.f, 0.f, 0.f);
        if (row0 + r < nrows)
            v = ((const float4*)(A + (size_t)(row0 + r) * 128))[k4];
        uint32_t* p = Apu + r * APITCH + k4 * 4;
        p[0] = cvt_tf32(v.x); p[1] = cvt_tf32(v.y);
        p[2] = cvt_tf32(v.z); p[3] = cvt_tf32(v.w);
    }
    __syncthreads();

    const int wrow = wid >> 1;
    const int wcol = wid & 1;
    const int g = lane >> 2, tg = lane & 3;

    float acc[2][8][4];
#pragma unroll
    for (int i = 0; i < 2; i++)
#pragma unroll
        for (int j = 0; j < 8; j++)
#pragma unroll
            for (int q = 0; q < 4; q++) acc[i][j][q] = 0.f;

    const uint32_t* BpBase = Bp + ((size_t)(wcol * 8) * 16) * 64 + lane * 2;

#pragma unroll 4
    for (int kt = 0; kt < 16; kt++) {
        uint32_t bf[8][2];
#pragma unroll
        for (int j = 0; j < 8; j++) {
            uint2 bv = *(const uint2*)(BpBase + (size_t)(j * 16 + kt) * 64);
            bf[j][0] = bv.x; bf[j][1] = bv.y;
        }
        uint32_t af[2][4];
#pragma unroll
        for (int i = 0; i < 2; i++) {
            int r = wrow * 32 + i * 16 + g;
            int c = kt * 8 + tg;
            af[i][0] = Apu[r * APITCH + c];
            af[i][1] = Apu[(r + 8) * APITCH + c];
            af[i][2] = Apu[r * APITCH + c + 4];
            af[i][3] = Apu[(r + 8) * APITCH + c + 4];
        }
#pragma unroll
        for (int i = 0; i < 2; i++)
#pragma unroll
            for (int j = 0; j < 8; j++)
                mma_tf32(acc[i][j], af[i], bf[j]);
    }

    // epilogue: half2 stores
#pragma unroll
    for (int i = 0; i < 2; i++) {
        int r = row0 + wrow * 32 + i * 16 + g;
#pragma unroll
        for (int j = 0; j < 8; j++) {
            int col = wcol * 64 + j * 8 + tg * 2;
            if (r < nrows)
                *(__half2*)(C + (size_t)r * 128 + col) =
                    __floats2half2_rn(acc[i][j][0], acc[i][j][1]);
            if (r + 8 < nrows)
                *(__half2*)(C + (size_t)(r + 8) * 128 + col) =
                    __floats2half2_rn(acc[i][j][2], acc[i][j][3]);
        }
    }
}

// ---------------- aggregation (fp16 gather -> fp32 accumulate) ----------------
__global__ __launch_bounds__(128) void k_aggregate(const __half* __restrict__ H,
                                                   const float* __restrict__ bias,
                                                   float* __restrict__ out,
                                                   float* __restrict__ out2,
                                                   int n, int relu) {
    int warp = threadIdx.x >> 5;
    int lane = threadIdx.x & 31;
    int node = blockIdx.x * 4 + warp;
    if (node >= n) return;

    const __half2* H2 = (const __half2*)H;  // 64 half2 per row
    const int loff = lane * 2;

    float di = g_dinv[node];
    float di2 = di * di;
    uint2 sraw = *(const uint2*)(H2 + (size_t)node * 64 + loff);
    float2 s0f = __half22float2(*(__half2*)&sraw.x);
    float2 s1f = __half22float2(*(__half2*)&sraw.y);
    float4 a0 = make_float4(s0f.x * di2, s0f.y * di2, s1f.x * di2, s1f.y * di2);
    float4 a1 = make_float4(0.f, 0.f, 0.f, 0.f);

    int e0 = g_rowptr[node], e1 = g_rowptr[node + 1];
    int e = e0;
    for (; e + 1 < e1; e += 2) {
        int   sA = g_esrc[e],  sB = g_esrc[e + 1];
        float mA = g_enorm[e], mB = g_enorm[e + 1];
        uint2 rA = *(const uint2*)(H2 + (size_t)sA * 64 + loff);
        uint2 rB = *(const uint2*)(H2 + (size_t)sB * 64 + loff);
        float2 a = __half22float2(*(__half2*)&rA.x);
        float2 b = __half22float2(*(__half2*)&rA.y);
        float2 c = __half22float2(*(__half2*)&rB.x);
        float2 d = __half22float2(*(__half2*)&rB.y);
        a0.x = fmaf(a.x, mA, a0.x); a0.y = fmaf(a.y, mA, a0.y);
        a0.z = fmaf(b.x, mA, a0.z); a0.w = fmaf(b.y, mA, a0.w);
        a1.x = fmaf(c.x, mB, a1.x); a1.y = fmaf(c.y, mB, a1.y);
        a1.z = fmaf(d.x, mB, a1.z); a1.w = fmaf(d.y, mB, a1.w);
    }
    if (e < e1) {
        int   sA = g_esrc[e];
        float mA = g_enorm[e];
        uint2 rA = *(const uint2*)(H2 + (size_t)sA * 64 + loff);
        float2 a = __half22float2(*(__half2*)&rA.x);
        float2 b = __half22float2(*(__half2*)&rA.y);
        a0.x = fmaf(a.x, mA, a0.x); a0.y = fmaf(a.y, mA, a0.y);
        a0.z = fmaf(b.x, mA, a0.z); a0.w = fmaf(b.y, mA, a0.w);
    }

    float4 bset = *(const float4*)(bias + lane * 4);
    float4 o = make_float4(a0.x + a1.x + bset.x, a0.y + a1.y + bset.y,
                           a0.z + a1.z + bset.z, a0.w + a1.w + bset.w);
    if (relu) {
        o.x = fmaxf(o.x, 0.f); o.y = fmaxf(o.y, 0.f);
        o.z = fmaxf(o.z, 0.f); o.w = fmaxf(o.w, 0.f);
    }
    size_t off = (size_t)node * 128 + lane * 4;
    *(float4*)(out + off) = o;
    if (out2) *(float4*)(out2 + off) = o;
}

// ---------------- launch ----------------
extern "C" void kernel_launch(void* const* d_in, const int* in_sizes, int n_in,
                              void* d_out, int out_size) {
    const float* x  = (const float*)d_in[0];
    const int*   ei = (const int*)d_in[1];
    const float* W1 = (const float*)d_in[2];
    const float* b1 = (const float*)d_in[3];
    const float* W2 = (const float*)d_in[4];
    const float* b2 = (const float*)d_in[5];
    const float* W3 = (const float*)d_in[6];
    const float* b3 = (const float*)d_in[7];

    int N = in_sizes[0] / FDIM;
    if (N > NN) N = NN;
    int E = in_sizes[1] / 2;
    if (E > EMAX) E = EMAX;

    static float* t = nullptr;
    static float* h = nullptr;
    static uint32_t* bp = nullptr;
    static int* cntp = nullptr;
    static int* cnt2p = nullptr;
    static bool inited = false;
    if (!inited) {
        cudaGetSymbolAddress((void**)&t, g_t);
        cudaGetSymbolAddress((void**)&h, g_h);
        cudaGetSymbolAddress((void**)&bp, g_Bp);
        cudaGetSymbolAddress((void**)&cntp, g_cnt);
        cudaGetSymbolAddress((void**)&cnt2p, g_cnt2);
        cudaFuncSetAttribute(k_gemm_mma, cudaFuncAttributeMaxDynamicSharedMemorySize,
                             SMEM_GEMM);
        inited = true;
    }
    __half* th = (__half*)t;
    uint32_t* Bp1 = bp;
    uint32_t* Bp2 = bp + 16384;
    uint32_t* Bp3 = bp + 2 * 16384;

    const int nScan = (N + 1023) / 1024;

    // setup: weight fragments + CSR build
    k_bperm3<<<96, 256>>>(W1, W2, W3);
    cudaMemsetAsync(cntp, 0, (size_t)N * sizeof(int));
    cudaMemsetAsync(cnt2p, 0, (size_t)N * sizeof(int));
    k_count<<<(E + 255) / 256, 256>>>(ei, E);
    k_scan1<<<nScan, 1024>>>(N);
    k_scan3b<<<nScan, 1024>>>(N, E);
    k_scatter<<<(E + 255) / 256, 256>>>(ei, E);

    const int gGemm = (N + 127) / 128;
    const int gAgg  = (N + 3) / 4;
    float* out = (float*)d_out;
    int half = N * FDIM;
    float* out2 = (out_size >= 2 * half) ? out + half : nullptr;

    k_gemm_mma<<<gGemm, 256, SMEM_GEMM>>>(x, Bp1, th, N);
    k_aggregate<<<gAgg, 128>>>(th, b1, h, nullptr, N, 1);
    k_gemm_mma<<<gGemm, 256, SMEM_GEMM>>>(h, Bp2, th, N);
    k_aggregate<<<gAgg, 128>>>(th, b2, h, nullptr, N, 1);
    k_gemm_mma<<<gGemm, 256, SMEM_GEMM>>>(h, Bp3, th, N);
    k_aggregate<<<gAgg, 128>>>(th, b3, out, out2, N, 0);
}